// round 2
// baseline (speedup 1.0000x reference)
#include <cuda_runtime.h>
#include <cuda_bf16.h>
#include <math_constants.h>

// Problem constants (fixed shapes from setup_inputs)
#define N_Q   4096
#define N_T   16384
#define M_SUB 64
#define KSUB  256
#define DSUB  8
#define DIM   512   // M_SUB * DSUB

// Scratch: __device__ globals (allocation-free per harness rules)
static __device__ int   g_codes[N_Q * M_SUB];          // 1 MB
static __device__ float g_xdec [N_Q * DIM];            // 8 MB
static __device__ float g_ydec [N_T * DIM];            // 32 MB

// ---------------------------------------------------------------------------
// Encode: codes[i,s] = argmin_k ( ||cen[s,k]||^2 - 2 * x[i,s*8:..] . cen[s,k] )
// One block per query, 8 warps; each warp handles subspaces s = warp, warp+8.
// Lane l covers centroids k = l + 32*j (j ascending keeps first-min tiebreak).
// ---------------------------------------------------------------------------
__global__ void __launch_bounds__(256) encode_kernel(const float* __restrict__ x,
                                                     const float* __restrict__ cen)
{
    int i    = blockIdx.x;
    int warp = threadIdx.x >> 5;
    int lane = threadIdx.x & 31;

    for (int s = warp; s < M_SUB; s += 8) {
        const float* xp = x + i * DIM + s * DSUB;
        float xv[DSUB];
#pragma unroll
        for (int d = 0; d < DSUB; d++) xv[d] = __ldg(xp + d);

        float best = CUDART_INF_F;
        int   bidx = 0;
#pragma unroll
        for (int j = 0; j < KSUB / 32; j++) {
            int k = lane + j * 32;
            const float* cp = cen + (size_t)(s * KSUB + k) * DSUB;
            float4 c0 = *(const float4*)cp;
            float4 c1 = *(const float4*)(cp + 4);
            float dot = xv[0]*c0.x + xv[1]*c0.y + xv[2]*c0.z + xv[3]*c0.w
                      + xv[4]*c1.x + xv[5]*c1.y + xv[6]*c1.z + xv[7]*c1.w;
            float n2  = c0.x*c0.x + c0.y*c0.y + c0.z*c0.z + c0.w*c0.w
                      + c1.x*c1.x + c1.y*c1.y + c1.z*c1.z + c1.w*c1.w;
            float dis = n2 - 2.0f * dot;
            if (dis < best) { best = dis; bidx = k; }
        }
        // warp argmin reduce (smaller index wins on exact ties)
#pragma unroll
        for (int off = 16; off > 0; off >>= 1) {
            float od = __shfl_xor_sync(0xffffffffu, best, off);
            int   oi = __shfl_xor_sync(0xffffffffu, bidx, off);
            if (od < best || (od == best && oi < bidx)) { best = od; bidx = oi; }
        }
        if (lane == 0) g_codes[i * M_SUB + s] = bidx;
    }
}

// ---------------------------------------------------------------------------
// Decode: out[row, s*8 + d] = cen[s, code[row,s], d]
// One thread per (row, subspace): copies 8 floats (two float4, coalesced 32B).
// ---------------------------------------------------------------------------
__global__ void decode_from_gcodes(const float* __restrict__ cen, int total)
{
    int t = blockIdx.x * blockDim.x + threadIdx.x;
    if (t >= total) return;
    int s    = t & (M_SUB - 1);
    int code = g_codes[t];
    const float4* cp = (const float4*)(cen + (size_t)(s * KSUB + code) * DSUB);
    float4* op = (float4*)(g_xdec + (size_t)t * DSUB);
    op[0] = cp[0];
    op[1] = cp[1];
}

__global__ void decode_targets(const int* __restrict__ tgt,
                               const float* __restrict__ cen, int total)
{
    int t = blockIdx.x * blockDim.x + threadIdx.x;
    if (t >= total) return;
    int s    = t & (M_SUB - 1);
    int code = tgt[t];
    const float4* cp = (const float4*)(cen + (size_t)(s * KSUB + code) * DSUB);
    float4* op = (float4*)(g_ydec + (size_t)t * DSUB);
    op[0] = cp[0];
    op[1] = cp[1];
}

// ---------------------------------------------------------------------------
// SGEMM (double-buffered): C[i,j] = sum_k A[i,k] * B[j,k]
//   A = g_xdec [4096, 512], B = g_ydec [16384, 512], C = sim [4096, 16384]
// 128x128 block tile, BK=16, 256 threads, 8x8 microtile split into 4x4 quads
// (cols tx*4 / 64+tx*4; rows ty*4 / 64+ty*4) for conflict-free LDS.128.
// Two-stage smem pipeline: prefetch slab k+1 to registers while computing k.
// ---------------------------------------------------------------------------
#define BK 16
__global__ void __launch_bounds__(256) sgemm_nt_kernel(float* __restrict__ C)
{
    __shared__ float As[2][BK][132];
    __shared__ float Bs[2][BK][132];

    const int t  = threadIdx.x;
    const int tx = t & 15;
    const int ty = t >> 4;
    const int i0 = blockIdx.y * 128;
    const int j0 = blockIdx.x * 128;

    const float* __restrict__ A = g_xdec;
    const float* __restrict__ B = g_ydec;

    // Per-thread load coordinates: thread handles float4s f = t and t+256
    // of the 512-float4 (128 row x 4 float4) tile.
    const int row0 = t >> 2;              // 0..63
    const int c40  = (t & 3) * 4;         // 0,4,8,12
    const int row1 = (t + 256) >> 2;      // 64..127
    const int c41  = c40;                 // same column phase

    float acc[8][8];
#pragma unroll
    for (int u = 0; u < 8; u++)
#pragma unroll
        for (int v = 0; v < 8; v++) acc[u][v] = 0.0f;

    // ---- preload slab 0 into buffer 0 ----
    {
        float4 va0 = *(const float4*)&A[(size_t)(i0 + row0) * DIM + c40];
        float4 vb0 = *(const float4*)&B[(size_t)(j0 + row0) * DIM + c40];
        float4 va1 = *(const float4*)&A[(size_t)(i0 + row1) * DIM + c41];
        float4 vb1 = *(const float4*)&B[(size_t)(j0 + row1) * DIM + c41];
        As[0][c40+0][row0] = va0.x; As[0][c40+1][row0] = va0.y;
        As[0][c40+2][row0] = va0.z; As[0][c40+3][row0] = va0.w;
        Bs[0][c40+0][row0] = vb0.x; Bs[0][c40+1][row0] = vb0.y;
        Bs[0][c40+2][row0] = vb0.z; Bs[0][c40+3][row0] = vb0.w;
        As[0][c41+0][row1] = va1.x; As[0][c41+1][row1] = va1.y;
        As[0][c41+2][row1] = va1.z; As[0][c41+3][row1] = va1.w;
        Bs[0][c41+0][row1] = vb1.x; Bs[0][c41+1][row1] = vb1.y;
        Bs[0][c41+2][row1] = vb1.z; Bs[0][c41+3][row1] = vb1.w;
    }
    __syncthreads();

    int buf = 0;
#pragma unroll 1
    for (int k0 = BK; k0 <= DIM; k0 += BK) {
        // ---- prefetch next slab into registers (overlaps with compute) ----
        float4 va0, vb0, va1, vb1;
        const bool have_next = (k0 < DIM);
        if (have_next) {
            va0 = *(const float4*)&A[(size_t)(i0 + row0) * DIM + k0 + c40];
            vb0 = *(const float4*)&B[(size_t)(j0 + row0) * DIM + k0 + c40];
            va1 = *(const float4*)&A[(size_t)(i0 + row1) * DIM + k0 + c41];
            vb1 = *(const float4*)&B[(size_t)(j0 + row1) * DIM + k0 + c41];
        }

        // ---- compute on current buffer ----
#pragma unroll
        for (int kk = 0; kk < BK; kk++) {
            float4 a0 = *(const float4*)&As[buf][kk][ty * 4];
            float4 a1 = *(const float4*)&As[buf][kk][64 + ty * 4];
            float4 b0 = *(const float4*)&Bs[buf][kk][tx * 4];
            float4 b1 = *(const float4*)&Bs[buf][kk][64 + tx * 4];
            float ar[8] = {a0.x, a0.y, a0.z, a0.w, a1.x, a1.y, a1.z, a1.w};
            float br[8] = {b0.x, b0.y, b0.z, b0.w, b1.x, b1.y, b1.z, b1.w};
#pragma unroll
            for (int u = 0; u < 8; u++)
#pragma unroll
                for (int v = 0; v < 8; v++)
                    acc[u][v] = fmaf(ar[u], br[v], acc[u][v]);
        }

        // ---- store prefetched slab into the other buffer ----
        if (have_next) {
            int nb = buf ^ 1;
            As[nb][c40+0][row0] = va0.x; As[nb][c40+1][row0] = va0.y;
            As[nb][c40+2][row0] = va0.z; As[nb][c40+3][row0] = va0.w;
            Bs[nb][c40+0][row0] = vb0.x; Bs[nb][c40+1][row0] = vb0.y;
            Bs[nb][c40+2][row0] = vb0.z; Bs[nb][c40+3][row0] = vb0.w;
            As[nb][c41+0][row1] = va1.x; As[nb][c41+1][row1] = va1.y;
            As[nb][c41+2][row1] = va1.z; As[nb][c41+3][row1] = va1.w;
            Bs[nb][c41+0][row1] = vb1.x; Bs[nb][c41+1][row1] = vb1.y;
            Bs[nb][c41+2][row1] = vb1.z; Bs[nb][c41+3][row1] = vb1.w;
            __syncthreads();
            buf = nb;
        }
    }

    // Write back: rows ty*4(+64), cols tx*4(+64), float4 stores.
#pragma unroll
    for (int u = 0; u < 8; u++) {
        int row = i0 + ((u < 4) ? (ty * 4 + u) : (64 + ty * 4 + (u - 4)));
        float4 v0 = make_float4(acc[u][0], acc[u][1], acc[u][2], acc[u][3]);
        float4 v1 = make_float4(acc[u][4], acc[u][5], acc[u][6], acc[u][7]);
        *(float4*)&C[(size_t)row * N_T + j0 + tx * 4]      = v0;
        *(float4*)&C[(size_t)row * N_T + j0 + 64 + tx * 4] = v1;
    }
}

// ---------------------------------------------------------------------------
// Launch
// ---------------------------------------------------------------------------
extern "C" void kernel_launch(void* const* d_in, const int* in_sizes, int n_in,
                              void* d_out, int out_size)
{
    const float* x   = (const float*)d_in[0];  // [4096, 512]
    const float* cen = (const float*)d_in[1];  // [64, 256, 8]
    const int*   tgt = (const int*)  d_in[2];  // [16384, 64]
    float*       sim = (float*)d_out;          // [4096, 16384]

    encode_kernel<<<N_Q, 256>>>(x, cen);

    {
        int total = N_Q * M_SUB;
        decode_from_gcodes<<<(total + 255) / 256, 256>>>(cen, total);
    }
    {
        int total = N_T * M_SUB;
        decode_targets<<<(total + 255) / 256, 256>>>(tgt, cen, total);
    }

    dim3 grid(N_T / 128, N_Q / 128);  // (128, 32)
    sgemm_nt_kernel<<<grid, 256>>>(sim);
}

// round 8
// speedup vs baseline: 2.1912x; 2.1912x over previous
#include <cuda_runtime.h>
#include <cuda_bf16.h>
#include <math_constants.h>
#include <cstdint>

// Problem constants (fixed shapes from setup_inputs)
#define N_Q   4096
#define N_T   16384
#define M_SUB 64
#define KSUB  256
#define DSUB  8
#define DIM   512    // M_SUB * DSUB
#define NKC   8      // K chunks of 64 (DIM / 64)

// ---------------------------------------------------------------------------
// Device-global scratch (allocation-free per harness rules)
// ---------------------------------------------------------------------------
static __device__ uint4 g_cenh[M_SUB * KSUB];            // codebook hi (8 bf16 = 16B)
static __device__ uint4 g_cenl[M_SUB * KSUB];            // codebook lo
static __device__ uint4 g_Ahi [N_Q * M_SUB];             // 4 MB  decoded queries hi
static __device__ uint4 g_Alo [N_Q * M_SUB];             // 4 MB
static __device__ uint4 g_Bhi [N_T * M_SUB];             // 16 MB decoded targets hi
static __device__ uint4 g_Blo [N_T * M_SUB];             // 16 MB

// ---------------------------------------------------------------------------
// PTX helpers (base ISA only: cp.async sm_80, ldmatrix sm_75, mma.sync sm_80)
// ---------------------------------------------------------------------------
__device__ __forceinline__ uint32_t smem_u32(const void* p) {
    uint32_t a;
    asm("{ .reg .u64 t; cvta.to.shared.u64 t, %1; cvt.u32.u64 %0, t; }" : "=r"(a) : "l"(p));
    return a;
}
__device__ __forceinline__ void cp_async16(uint32_t dst, const void* src) {
    asm volatile("cp.async.cg.shared.global [%0], [%1], 16;" :: "r"(dst), "l"(src) : "memory");
}
__device__ __forceinline__ void cp_commit() {
    asm volatile("cp.async.commit_group;" ::: "memory");
}
__device__ __forceinline__ void cp_wait1() {
    asm volatile("cp.async.wait_group 1;" ::: "memory");
}
__device__ __forceinline__ void cp_wait0() {
    asm volatile("cp.async.wait_group 0;" ::: "memory");
}
__device__ __forceinline__ void ldsm4(uint32_t* r, uint32_t addr) {
    asm volatile("ldmatrix.sync.aligned.m8n8.x4.shared.b16 {%0,%1,%2,%3}, [%4];"
                 : "=r"(r[0]), "=r"(r[1]), "=r"(r[2]), "=r"(r[3]) : "r"(addr));
}
__device__ __forceinline__ void mma16816(float* d, const uint32_t* a, uint32_t b0, uint32_t b1) {
    asm volatile(
        "mma.sync.aligned.m16n8k16.row.col.f32.bf16.bf16.f32 "
        "{%0,%1,%2,%3}, {%4,%5,%6,%7}, {%8,%9}, {%0,%1,%2,%3};"
        : "+f"(d[0]), "+f"(d[1]), "+f"(d[2]), "+f"(d[3])
        : "r"(a[0]), "r"(a[1]), "r"(a[2]), "r"(a[3]), "r"(b0), "r"(b1));
}

// ---------------------------------------------------------------------------
// Codebook split: hi = bf16(x), lo = bf16(x - hi)
// ---------------------------------------------------------------------------
__global__ void convert_codebook(const float* __restrict__ cen)
{
    int t = blockIdx.x * blockDim.x + threadIdx.x;
    if (t >= M_SUB * KSUB) return;
    const float4* cp = (const float4*)(cen + (size_t)t * DSUB);
    float4 a = cp[0], b = cp[1];
    float v[8] = {a.x, a.y, a.z, a.w, b.x, b.y, b.z, b.w};
    __nv_bfloat16 h[8], l[8];
#pragma unroll
    for (int d = 0; d < 8; d++) {
        h[d] = __float2bfloat16(v[d]);
        l[d] = __float2bfloat16(v[d] - __bfloat162float(h[d]));
    }
    g_cenh[t] = *(const uint4*)h;
    g_cenl[t] = *(const uint4*)l;
}

// ---------------------------------------------------------------------------
// Encode + decode fused: argmin over centroids, then lane 0 writes the
// split-bf16 decoded query row directly (it already holds the best index).
// ---------------------------------------------------------------------------
__global__ void __launch_bounds__(256) encode_kernel(const float* __restrict__ x,
                                                     const float* __restrict__ cen)
{
    int i    = blockIdx.x;
    int warp = threadIdx.x >> 5;
    int lane = threadIdx.x & 31;

    for (int s = warp; s < M_SUB; s += 8) {
        const float* xp = x + i * DIM + s * DSUB;
        float xv[DSUB];
#pragma unroll
        for (int d = 0; d < DSUB; d++) xv[d] = __ldg(xp + d);

        float best = CUDART_INF_F;
        int   bidx = 0;
#pragma unroll
        for (int j = 0; j < KSUB / 32; j++) {
            int k = lane + j * 32;
            const float* cp = cen + (size_t)(s * KSUB + k) * DSUB;
            float4 c0 = *(const float4*)cp;
            float4 c1 = *(const float4*)(cp + 4);
            float dot = xv[0]*c0.x + xv[1]*c0.y + xv[2]*c0.z + xv[3]*c0.w
                      + xv[4]*c1.x + xv[5]*c1.y + xv[6]*c1.z + xv[7]*c1.w;
            float n2  = c0.x*c0.x + c0.y*c0.y + c0.z*c0.z + c0.w*c0.w
                      + c1.x*c1.x + c1.y*c1.y + c1.z*c1.z + c1.w*c1.w;
            float dis = n2 - 2.0f * dot;
            if (dis < best) { best = dis; bidx = k; }
        }
#pragma unroll
        for (int off = 16; off > 0; off >>= 1) {
            float od = __shfl_xor_sync(0xffffffffu, best, off);
            int   oi = __shfl_xor_sync(0xffffffffu, bidx, off);
            if (od < best || (od == best && oi < bidx)) { best = od; bidx = oi; }
        }
        if (lane == 0) {
            int src = s * KSUB + bidx;
            g_Ahi[i * M_SUB + s] = g_cenh[src];
            g_Alo[i * M_SUB + s] = g_cenl[src];
        }
    }
}

// ---------------------------------------------------------------------------
// Decode targets: one thread per (row, subspace)
// ---------------------------------------------------------------------------
__global__ void decode_y_kernel(const int* __restrict__ tgt, int total)
{
    int t = blockIdx.x * blockDim.x + threadIdx.x;
    if (t >= total) return;
    int s    = t & (M_SUB - 1);
    int code = tgt[t];
    int src  = s * KSUB + code;
    g_Bhi[t] = g_cenh[src];
    g_Blo[t] = g_cenl[src];
}

// ---------------------------------------------------------------------------
// Split-bf16 GEMM via base-ISA mma.sync (HMMA):
//   C[i,j] = Ahi.Bhi + Ahi.Blo + Alo.Bhi   (exact fp32 up to ~2^-16 dropped term)
// CTA tile 128x128, 8 warps (4x2), warp tile 32x64 (2 m16 x 8 n8 mma tiles).
// Per 64-wide K chunk: load Ahi/Alo/Bhi/Blo tiles ONCE, run all 3 passes.
// cp.async double buffer (2 x 64KB smem), xor-swizzled for conflict-free ldmatrix.
// ---------------------------------------------------------------------------
#define TILE_BYTES  16384                 // 128 rows x 64 bf16 (128B/row)
#define STAGE_BYTES (4 * TILE_BYTES)      // Ahi | Alo | Bhi | Blo
#define SMEM_TOTAL  (2 * STAGE_BYTES)     // 128 KB

__device__ __forceinline__ void issue_chunk_loads(
    uint32_t sbase, int kc, int tid, int i0, int j0)
{
    const char* mats[4] = { (const char*)g_Ahi, (const char*)g_Alo,
                            (const char*)g_Bhi, (const char*)g_Blo };
    uint32_t stage = sbase + (uint32_t)(kc & 1) * STAGE_BYTES;
    int colb = kc * 128;                        // byte offset of this K chunk in a 1KB row
#pragma unroll
    for (int it = 0; it < 16; it++) {
        int idx  = tid + it * 256;              // 0..4095
        int mat  = idx >> 10;                   // 0 Ahi, 1 Alo, 2 Bhi, 3 Blo
        int rr   = (idx >> 3) & 127;            // tile row
        int c    = idx & 7;                     // 16B chunk in 128B row
        int grow = ((mat >> 1) ? j0 : i0) + rr;
        const char* src = mats[mat] + (size_t)grow * 1024 + colb + c * 16;
        uint32_t dst = stage + (uint32_t)mat * TILE_BYTES
                     + (uint32_t)rr * 128 + (uint32_t)((c ^ (rr & 7)) << 4);
        cp_async16(dst, src);
    }
}

__global__ void __launch_bounds__(256, 1) pq_mma_gemm(float* __restrict__ C)
{
    extern __shared__ char smem[];
    uint32_t sbase = smem_u32(smem);
    const int tid  = threadIdx.x;
    const int lane = tid & 31;
    const int warp = tid >> 5;
    const int wm   = warp >> 1;      // 0..3  (M direction, 32 rows each)
    const int wn   = warp & 1;       // 0..1  (N direction, 64 cols each)
    const int i0   = blockIdx.y * 128;
    const int j0   = blockIdx.x * 128;

    const int lrow = lane & 15;      // ldmatrix row within 16-row tile
    const int lk   = lane >> 4;      // ldmatrix k-half (0/1)

    float acc[2][8][4];
#pragma unroll
    for (int mt = 0; mt < 2; mt++)
#pragma unroll
        for (int nt = 0; nt < 8; nt++)
#pragma unroll
            for (int e = 0; e < 4; e++) acc[mt][nt][e] = 0.0f;

    // prologue: chunk 0
    issue_chunk_loads(sbase, 0, tid, i0, j0);
    cp_commit();

#pragma unroll 1
    for (int kc = 0; kc < NKC; kc++) {
        if (kc + 1 < NKC) issue_chunk_loads(sbase, kc + 1, tid, i0, j0);
        cp_commit();
        if (kc + 1 < NKC) cp_wait1(); else cp_wait0();
        __syncthreads();

        uint32_t stage = sbase + (uint32_t)(kc & 1) * STAGE_BYTES;
        uint32_t aBase = stage + (uint32_t)(wm * 32 + lrow) * 128;
        uint32_t bBase = stage + 2 * TILE_BYTES + (uint32_t)(wn * 64 + lrow) * 128;

#pragma unroll
        for (int ks = 0; ks < 4; ks++) {
            uint32_t sw = (uint32_t)(((ks * 2 + lk) ^ (lrow & 7)) << 4);
            uint32_t ah[8], al[8], bh[16], bl[16];
#pragma unroll
            for (int mt = 0; mt < 2; mt++) {
                ldsm4(ah + 4 * mt, aBase + (uint32_t)mt * 2048 + sw);
                ldsm4(al + 4 * mt, aBase + TILE_BYTES + (uint32_t)mt * 2048 + sw);
            }
#pragma unroll
            for (int nb = 0; nb < 4; nb++) {
                ldsm4(bh + 4 * nb, bBase + (uint32_t)nb * 2048 + sw);
                ldsm4(bl + 4 * nb, bBase + TILE_BYTES + (uint32_t)nb * 2048 + sw);
            }
#pragma unroll
            for (int mt = 0; mt < 2; mt++)
#pragma unroll
                for (int nt = 0; nt < 8; nt++) {
                    int nb  = nt >> 1;
                    int sel = nt & 1;
                    uint32_t bh0 = bh[4 * nb + sel], bh1 = bh[4 * nb + sel + 2];
                    uint32_t bl0 = bl[4 * nb + sel], bl1 = bl[4 * nb + sel + 2];
                    mma16816(acc[mt][nt], ah + 4 * mt, bh0, bh1);  // hi.hi
                    mma16816(acc[mt][nt], ah + 4 * mt, bl0, bl1);  // hi.lo
                    mma16816(acc[mt][nt], al + 4 * mt, bh0, bh1);  // lo.hi
                }
        }
        __syncthreads();
    }

    // ---- epilogue: direct stores (each lane: float2 per (mt,nt,half)) ----
    const int g  = lane >> 2;        // accumulator row group (0..7)
    const int tg = lane & 3;         // col pair index
#pragma unroll
    for (int mt = 0; mt < 2; mt++) {
        int row = i0 + wm * 32 + mt * 16 + g;
#pragma unroll
        for (int nt = 0; nt < 8; nt++) {
            int col = j0 + wn * 64 + nt * 8 + tg * 2;
            *(float2*)&C[(size_t)row * N_T + col] =
                make_float2(acc[mt][nt][0], acc[mt][nt][1]);
            *(float2*)&C[(size_t)(row + 8) * N_T + col] =
                make_float2(acc[mt][nt][2], acc[mt][nt][3]);
        }
    }
}

// ---------------------------------------------------------------------------
// Launch
// ---------------------------------------------------------------------------
extern "C" void kernel_launch(void* const* d_in, const int* in_sizes, int n_in,
                              void* d_out, int out_size)
{
    const float* x   = (const float*)d_in[0];  // [4096, 512]
    const float* cen = (const float*)d_in[1];  // [64, 256, 8]
    const int*   tgt = (const int*)  d_in[2];  // [16384, 64]
    float*       sim = (float*)d_out;          // [4096, 16384]

    cudaFuncSetAttribute(pq_mma_gemm, cudaFuncAttributeMaxDynamicSharedMemorySize, SMEM_TOTAL);

    convert_codebook<<<(M_SUB * KSUB + 255) / 256, 256>>>(cen);
    encode_kernel<<<N_Q, 256>>>(x, cen);
    decode_y_kernel<<<(N_T * M_SUB + 255) / 256, 256>>>(tgt, N_T * M_SUB);

    dim3 grid(N_T / 128, N_Q / 128);  // (128, 32)
    pq_mma_gemm<<<grid, 256, SMEM_TOTAL>>>(sim);
}

// round 9
// speedup vs baseline: 2.3838x; 1.0879x over previous
#include <cuda_runtime.h>
#include <cuda_bf16.h>
#include <math_constants.h>
#include <cstdint>

// Problem constants (fixed shapes from setup_inputs)
#define N_Q   4096
#define N_T   16384
#define M_SUB 64
#define KSUB  256
#define DSUB  8
#define DIM   512    // M_SUB * DSUB
#define NKC   8      // K chunks of 64 (DIM / 64)

// ---------------------------------------------------------------------------
// Device-global scratch (allocation-free per harness rules)
// ---------------------------------------------------------------------------
static __device__ uint4 g_cenh [M_SUB * KSUB];           // codebook hi (8 bf16 = 16B)
static __device__ uint4 g_cenl [M_SUB * KSUB];           // codebook lo
static __device__ float g_norm2[M_SUB * KSUB];           // ||cen||^2 (fp32)
static __device__ uint4 g_Ahi [N_Q * M_SUB];             // 4 MB  decoded queries hi
static __device__ uint4 g_Alo [N_Q * M_SUB];             // 4 MB
static __device__ uint4 g_Bhi [N_T * M_SUB];             // 16 MB decoded targets hi
static __device__ uint4 g_Blo [N_T * M_SUB];             // 16 MB

// ---------------------------------------------------------------------------
// PTX helpers (base ISA only: cp.async sm_80, ldmatrix sm_75, mma.sync sm_80)
// ---------------------------------------------------------------------------
__device__ __forceinline__ uint32_t smem_u32(const void* p) {
    uint32_t a;
    asm("{ .reg .u64 t; cvta.to.shared.u64 t, %1; cvt.u32.u64 %0, t; }" : "=r"(a) : "l"(p));
    return a;
}
__device__ __forceinline__ void cp_async16(uint32_t dst, const void* src) {
    asm volatile("cp.async.cg.shared.global [%0], [%1], 16;" :: "r"(dst), "l"(src) : "memory");
}
__device__ __forceinline__ void cp_commit() {
    asm volatile("cp.async.commit_group;" ::: "memory");
}
__device__ __forceinline__ void cp_wait1() {
    asm volatile("cp.async.wait_group 1;" ::: "memory");
}
__device__ __forceinline__ void cp_wait0() {
    asm volatile("cp.async.wait_group 0;" ::: "memory");
}
__device__ __forceinline__ void ldsm4(uint32_t* r, uint32_t addr) {
    asm volatile("ldmatrix.sync.aligned.m8n8.x4.shared.b16 {%0,%1,%2,%3}, [%4];"
                 : "=r"(r[0]), "=r"(r[1]), "=r"(r[2]), "=r"(r[3]) : "r"(addr));
}
__device__ __forceinline__ void mma16816(float* d, const uint32_t* a, uint32_t b0, uint32_t b1) {
    asm volatile(
        "mma.sync.aligned.m16n8k16.row.col.f32.bf16.bf16.f32 "
        "{%0,%1,%2,%3}, {%4,%5,%6,%7}, {%8,%9}, {%0,%1,%2,%3};"
        : "+f"(d[0]), "+f"(d[1]), "+f"(d[2]), "+f"(d[3])
        : "r"(a[0]), "r"(a[1]), "r"(a[2]), "r"(a[3]), "r"(b0), "r"(b1));
}

// ---------------------------------------------------------------------------
// Codebook split: hi = bf16(x), lo = bf16(x - hi); plus fp32 norm2
// ---------------------------------------------------------------------------
__global__ void convert_codebook(const float* __restrict__ cen)
{
    int t = blockIdx.x * blockDim.x + threadIdx.x;
    if (t >= M_SUB * KSUB) return;
    const float4* cp = (const float4*)(cen + (size_t)t * DSUB);
    float4 a = cp[0], b = cp[1];
    float v[8] = {a.x, a.y, a.z, a.w, b.x, b.y, b.z, b.w};
    __nv_bfloat16 h[8], l[8];
    float n2 = 0.0f;
#pragma unroll
    for (int d = 0; d < 8; d++) {
        h[d] = __float2bfloat16(v[d]);
        l[d] = __float2bfloat16(v[d] - __bfloat162float(h[d]));
        n2 += v[d] * v[d];
    }
    g_cenh[t]  = *(const uint4*)h;
    g_cenl[t]  = *(const uint4*)l;
    g_norm2[t] = n2;
}

// ---------------------------------------------------------------------------
// Encode + decode fused, 2 queries per block: argmin over centroids (exact
// fp32: dis = ||c||^2 - 2 x.c), lane 0 writes split-bf16 decoded rows.
// Centroid loads amortized across both queries.
// ---------------------------------------------------------------------------
__global__ void __launch_bounds__(256) encode_kernel(const float* __restrict__ x)
{
    int i0   = blockIdx.x * 2;
    int warp = threadIdx.x >> 5;
    int lane = threadIdx.x & 31;

    for (int s = warp; s < M_SUB; s += 8) {
        float xv0[DSUB], xv1[DSUB];
        const float* xp0 = x + (size_t)i0 * DIM + s * DSUB;
        const float* xp1 = xp0 + DIM;
#pragma unroll
        for (int d = 0; d < DSUB; d++) { xv0[d] = __ldg(xp0 + d); xv1[d] = __ldg(xp1 + d); }

        float best0 = CUDART_INF_F, best1 = CUDART_INF_F;
        int   bid0 = 0, bid1 = 0;
#pragma unroll
        for (int j = 0; j < KSUB / 32; j++) {
            int k = lane + j * 32;
            int ck = s * KSUB + k;
            // centroid in fp32 reconstructed exactly? No -- must read original?
            // We read the fp32 centroids via hi+lo? Not exact. Use norm2 + need
            // fp32 dot: we must load fp32 centroid values. Keep a dedicated load.
            const float4* cp = (const float4*)((const float*)nullptr);
            (void)cp;
            // (actual loads below use cen-derived fp32 table g_cenf)
            k = k; ck = ck;
            break;
        }
        // placeholder removed in real code path below
        (void)best0; (void)best1; (void)bid0; (void)bid1; (void)xv0; (void)xv1;
        break;
    }
}

// NOTE: the real encode is below; the stub above is unused. (Kept minimal to
// avoid dead-code divergence -- see encode2_kernel.)

__global__ void __launch_bounds__(256) encode2_kernel(const float* __restrict__ x,
                                                      const float* __restrict__ cen)
{
    int i0   = blockIdx.x * 2;
    int warp = threadIdx.x >> 5;
    int lane = threadIdx.x & 31;

    for (int s = warp; s < M_SUB; s += 8) {
        float xv0[DSUB], xv1[DSUB];
        const float* xp0 = x + (size_t)i0 * DIM + s * DSUB;
        const float* xp1 = xp0 + DIM;
#pragma unroll
        for (int d = 0; d < DSUB; d++) { xv0[d] = __ldg(xp0 + d); xv1[d] = __ldg(xp1 + d); }

        float best0 = CUDART_INF_F, best1 = CUDART_INF_F;
        int   bid0 = 0, bid1 = 0;
#pragma unroll
        for (int j = 0; j < KSUB / 32; j++) {
            int k  = lane + j * 32;
            int ck = s * KSUB + k;
            const float* cp = cen + (size_t)ck * DSUB;
            float4 c0 = *(const float4*)cp;
            float4 c1 = *(const float4*)(cp + 4);
            float n2 = g_norm2[ck];
            float d0 = xv0[0]*c0.x + xv0[1]*c0.y + xv0[2]*c0.z + xv0[3]*c0.w
                     + xv0[4]*c1.x + xv0[5]*c1.y + xv0[6]*c1.z + xv0[7]*c1.w;
            float d1 = xv1[0]*c0.x + xv1[1]*c0.y + xv1[2]*c0.z + xv1[3]*c0.w
                     + xv1[4]*c1.x + xv1[5]*c1.y + xv1[6]*c1.z + xv1[7]*c1.w;
            float dis0 = n2 - 2.0f * d0;
            float dis1 = n2 - 2.0f * d1;
            if (dis0 < best0) { best0 = dis0; bid0 = k; }
            if (dis1 < best1) { best1 = dis1; bid1 = k; }
        }
#pragma unroll
        for (int off = 16; off > 0; off >>= 1) {
            float o0 = __shfl_xor_sync(0xffffffffu, best0, off);
            int   i0x = __shfl_xor_sync(0xffffffffu, bid0, off);
            if (o0 < best0 || (o0 == best0 && i0x < bid0)) { best0 = o0; bid0 = i0x; }
            float o1 = __shfl_xor_sync(0xffffffffu, best1, off);
            int   i1x = __shfl_xor_sync(0xffffffffu, bid1, off);
            if (o1 < best1 || (o1 == best1 && i1x < bid1)) { best1 = o1; bid1 = i1x; }
        }
        if (lane == 0) {
            int src0 = s * KSUB + bid0;
            int src1 = s * KSUB + bid1;
            g_Ahi[(size_t)i0 * M_SUB + s]       = g_cenh[src0];
            g_Alo[(size_t)i0 * M_SUB + s]       = g_cenl[src0];
            g_Ahi[(size_t)(i0 + 1) * M_SUB + s] = g_cenh[src1];
            g_Alo[(size_t)(i0 + 1) * M_SUB + s] = g_cenl[src1];
        }
    }
}

// ---------------------------------------------------------------------------
// Decode targets: one thread per (row, subspace)
// ---------------------------------------------------------------------------
__global__ void decode_y_kernel(const int* __restrict__ tgt, int total)
{
    int t = blockIdx.x * blockDim.x + threadIdx.x;
    if (t >= total) return;
    int s    = t & (M_SUB - 1);
    int code = tgt[t];
    int src  = s * KSUB + code;
    g_Bhi[t] = g_cenh[src];
    g_Blo[t] = g_cenl[src];
}

// ---------------------------------------------------------------------------
// Split-bf16 GEMM via base-ISA mma.sync (HMMA):
//   C = Ahi.Bhi + Ahi.Blo + Alo.Bhi    (drops only ~2^-16 lo.lo term)
// CTA tile 256x128, 512 threads, 16 warps (8m x 2n), warp tile 32x64.
// K chunks of 64; per chunk load Ahi/Alo/Bhi/Blo once, 3 passes.
// B hi/lo processed sequentially through one 16-reg fragment buffer to fit
// the 128-reg/thread ceiling at 512 threads.
// cp.async double buffer (2 x 96KB smem), xor-swizzle for conflict-free ldsm.
// ---------------------------------------------------------------------------
#define A_TILE      32768                 // 256 rows x 128B
#define B_TILE      16384                 // 128 rows x 128B
#define STAGE_BYTES (2 * A_TILE + 2 * B_TILE)   // 98304
#define SMEM_TOTAL  (2 * STAGE_BYTES)           // 196608 (192 KB)

__device__ __forceinline__ void issue_chunk_loads(
    uint32_t sbase, int kc, int tid, int i0, int j0)
{
    uint32_t stage = sbase + (uint32_t)(kc & 1) * STAGE_BYTES;
    int colb = kc * 128;                        // byte offset of K chunk in 1KB row
#pragma unroll
    for (int it = 0; it < 12; it++) {
        int idx = tid + it * 512;               // 0..6143 (0..4095 A, 4096..6143 B)
        if (idx < 4096) {
            int mat = idx >> 11;                // 0 Ahi, 1 Alo
            int rr  = (idx >> 3) & 255;
            int c   = idx & 7;
            const char* src = (const char*)(mat ? g_Alo : g_Ahi)
                + (size_t)(i0 + rr) * 1024 + colb + c * 16;
            uint32_t dst = stage + (uint32_t)mat * A_TILE
                         + (uint32_t)rr * 128 + (uint32_t)((c ^ (rr & 7)) << 4);
            cp_async16(dst, src);
        } else {
            int idx2 = idx - 4096;
            int mat  = idx2 >> 10;              // 0 Bhi, 1 Blo
            int rr   = (idx2 >> 3) & 127;
            int c    = idx2 & 7;
            const char* src = (const char*)(mat ? g_Blo : g_Bhi)
                + (size_t)(j0 + rr) * 1024 + colb + c * 16;
            uint32_t dst = stage + 2 * A_TILE + (uint32_t)mat * B_TILE
                         + (uint32_t)rr * 128 + (uint32_t)((c ^ (rr & 7)) << 4);
            cp_async16(dst, src);
        }
    }
}

__global__ void __launch_bounds__(512, 1) pq_mma_gemm(float* __restrict__ C)
{
    extern __shared__ char smem[];
    uint32_t sbase = smem_u32(smem);
    const int tid  = threadIdx.x;
    const int lane = tid & 31;
    const int warp = tid >> 5;       // 0..15
    const int wm   = warp >> 1;      // 0..7  (M direction, 32 rows each)
    const int wn   = warp & 1;       // 0..1  (N direction, 64 cols each)
    const int i0   = blockIdx.y * 256;
    const int j0   = blockIdx.x * 128;

    const int lrow = lane & 15;      // ldmatrix row within 16-row tile
    const int lk   = lane >> 4;      // ldmatrix k-half (0/1)

    float acc[2][8][4];
#pragma unroll
    for (int mt = 0; mt < 2; mt++)
#pragma unroll
        for (int nt = 0; nt < 8; nt++)
#pragma unroll
            for (int e = 0; e < 4; e++) acc[mt][nt][e] = 0.0f;

    // prologue: chunk 0
    issue_chunk_loads(sbase, 0, tid, i0, j0);
    cp_commit();

#pragma unroll 1
    for (int kc = 0; kc < NKC; kc++) {
        if (kc + 1 < NKC) issue_chunk_loads(sbase, kc + 1, tid, i0, j0);
        cp_commit();
        if (kc + 1 < NKC) cp_wait1(); else cp_wait0();
        __syncthreads();

        uint32_t stage = sbase + (uint32_t)(kc & 1) * STAGE_BYTES;
        uint32_t aBase = stage + (uint32_t)(wm * 32 + lrow) * 128;          // Ahi
        uint32_t bBase = stage + 2 * A_TILE + (uint32_t)(wn * 64 + lrow) * 128; // Bhi

#pragma unroll
        for (int ks = 0; ks < 4; ks++) {
            uint32_t sw = (uint32_t)(((ks * 2 + lk) ^ (lrow & 7)) << 4);
            uint32_t ah[8], al[8], b[16];
#pragma unroll
            for (int mt = 0; mt < 2; mt++) {
                ldsm4(ah + 4 * mt, aBase + (uint32_t)mt * 2048 + sw);
                ldsm4(al + 4 * mt, aBase + A_TILE + (uint32_t)mt * 2048 + sw);
            }
            // ---- pass 1+2: B = Bhi ----
#pragma unroll
            for (int nb = 0; nb < 4; nb++)
                ldsm4(b + 4 * nb, bBase + (uint32_t)nb * 2048 + sw);
#pragma unroll
            for (int mt = 0; mt < 2; mt++)
#pragma unroll
                for (int nt = 0; nt < 8; nt++) {
                    int nb = nt >> 1, sel = nt & 1;
                    mma16816(acc[mt][nt], ah + 4 * mt, b[4*nb+sel], b[4*nb+sel+2]); // hi.hi
                    mma16816(acc[mt][nt], al + 4 * mt, b[4*nb+sel], b[4*nb+sel+2]); // lo.hi
                }
            // ---- pass 3: B = Blo ----
#pragma unroll
            for (int nb = 0; nb < 4; nb++)
                ldsm4(b + 4 * nb, bBase + B_TILE + (uint32_t)nb * 2048 + sw);
#pragma unroll
            for (int mt = 0; mt < 2; mt++)
#pragma unroll
                for (int nt = 0; nt < 8; nt++) {
                    int nb = nt >> 1, sel = nt & 1;
                    mma16816(acc[mt][nt], ah + 4 * mt, b[4*nb+sel], b[4*nb+sel+2]); // hi.lo
                }
        }
        __syncthreads();
    }

    // ---- epilogue: direct stores (each lane: float2 per (mt,nt,half)) ----
    const int g  = lane >> 2;        // accumulator row group (0..7)
    const int tg = lane & 3;         // col pair index
#pragma unroll
    for (int mt = 0; mt < 2; mt++) {
        int row = i0 + wm * 32 + mt * 16 + g;
#pragma unroll
        for (int nt = 0; nt < 8; nt++) {
            int col = j0 + wn * 64 + nt * 8 + tg * 2;
            *(float2*)&C[(size_t)row * N_T + col] =
                make_float2(acc[mt][nt][0], acc[mt][nt][1]);
            *(float2*)&C[(size_t)(row + 8) * N_T + col] =
                make_float2(acc[mt][nt][2], acc[mt][nt][3]);
        }
    }
}

// ---------------------------------------------------------------------------
// Launch
// ---------------------------------------------------------------------------
extern "C" void kernel_launch(void* const* d_in, const int* in_sizes, int n_in,
                              void* d_out, int out_size)
{
    const float* x   = (const float*)d_in[0];  // [4096, 512]
    const float* cen = (const float*)d_in[1];  // [64, 256, 8]
    const int*   tgt = (const int*)  d_in[2];  // [16384, 64]
    float*       sim = (float*)d_out;          // [4096, 16384]

    cudaFuncSetAttribute(pq_mma_gemm, cudaFuncAttributeMaxDynamicSharedMemorySize, SMEM_TOTAL);

    convert_codebook<<<(M_SUB * KSUB + 255) / 256, 256>>>(cen);
    encode2_kernel<<<N_Q / 2, 256>>>(x, cen);
    decode_y_kernel<<<(N_T * M_SUB + 255) / 256, 256>>>(tgt, N_T * M_SUB);

    dim3 grid(N_T / 128, N_Q / 256);  // (128, 16) = 2048 CTAs
    pq_mma_gemm<<<grid, 512, SMEM_TOTAL>>>(sim);
}